// round 14
// baseline (speedup 1.0000x reference)
#include <cuda_runtime.h>
#include <cuda_bf16.h>
#include <math.h>
#include <stdint.h>

#define NTOK 200704
#define NWIN 5184

__device__ __nv_bfloat16 g_xn [(size_t)NTOK * 128];
__device__ float         g_x2 [(size_t)NTOK * 128];
__device__ __nv_bfloat16 g_w1t[512 * 128];        // [n][k]
__device__ __nv_bfloat16 g_w2t[128 * 512];        // [n][k]
__device__ __nv_bfloat16 g_swb[4 * 56 * 72];      // padded spatial w [h][i(56)][j(72)]

__device__ __forceinline__ void cpasync16(uint32_t s, const void* g) {
    asm volatile("cp.async.cg.shared.global [%0], [%1], 16;\n" :: "r"(s), "l"(g));
}
__device__ __forceinline__ void cp_commit() { asm volatile("cp.async.commit_group;"); }
template<int N> __device__ __forceinline__ void cp_wait() {
    asm volatile("cp.async.wait_group %0;" :: "n"(N));
}
__device__ __forceinline__ uint32_t pack_bf16(float lo, float hi) {
    uint32_t r; asm("cvt.rn.bf16x2.f32 %0, %1, %2;" : "=r"(r) : "f"(hi), "f"(lo)); return r;
}
__device__ __forceinline__ float gelu_exact(float v) {
    return 0.5f * v * (1.0f + erff(v * 0.70710678118654752f));
}
__device__ __forceinline__ void ldmx4t(uint32_t* r, uint32_t saddr) {
    asm volatile("ldmatrix.sync.aligned.m8n8.x4.trans.shared.b16 {%0,%1,%2,%3}, [%4];"
        : "=r"(r[0]), "=r"(r[1]), "=r"(r[2]), "=r"(r[3]) : "r"(saddr));
}
__device__ __forceinline__ void ldmx4(uint32_t* r, uint32_t saddr) {
    asm volatile("ldmatrix.sync.aligned.m8n8.x4.shared.b16 {%0,%1,%2,%3}, [%4];"
        : "=r"(r[0]), "=r"(r[1]), "=r"(r[2]), "=r"(r[3]) : "r"(saddr));
}
__device__ __forceinline__ void ldmx2(uint32_t* r, uint32_t saddr) {
    asm volatile("ldmatrix.sync.aligned.m8n8.x2.shared.b16 {%0,%1}, [%2];"
        : "=r"(r[0]), "=r"(r[1]) : "r"(saddr));
}
#define MMA16816(d, a, b0, b1) \
    asm volatile("mma.sync.aligned.m16n8k16.row.col.f32.bf16.bf16.f32 " \
        "{%0,%1,%2,%3},{%4,%5,%6,%7},{%8,%9},{%0,%1,%2,%3};\n" \
        : "+f"((d)[0]), "+f"((d)[1]), "+f"((d)[2]), "+f"((d)[3]) \
        : "r"((a)[0]), "r"((a)[1]), "r"((a)[2]), "r"((a)[3]), "r"(b0), "r"(b1))

// ---------- weight prep ----------
__global__ void prep_weights(const float* __restrict__ w1, const float* __restrict__ w2,
                             const float* __restrict__ sw)
{
    int t = blockIdx.x * 256 + threadIdx.x;
    if (t < 512 * 128) {
        int n = t >> 7, k = t & 127;
        g_w1t[t] = __float2bfloat16(w1[k * 512 + n]);
        int n2 = t >> 9, k2 = t & 511;
        g_w2t[t] = __float2bfloat16(w2[k2 * 128 + n2]);
    }
    if (t < 4 * 56 * 72) {
        int h = t / 4032, r = t % 4032;
        int i = r / 72, j = r % 72;
        float v = (i < 49 && j < 49) ? sw[h * 2401 + i * 49 + j] : 0.0f;
        g_swb[t] = __float2bfloat16(v);
    }
}

// ---------- fused LN1 + TC window mix + residual + LN2 (interleaved pipeline) ----------
#define SXP 136
#define SWS 72
#define SYP 132
#define XNB 15232                       // one s_xn buffer: 56*136*2
#define OFF_W  (2*XNB)                  // 30464
#define OFF_Y  (OFF_W + 32256)          // 62720
#define PRE_SMEM (OFF_Y + 29568)        // 92288 -> 2 CTA/SM

__global__ void __launch_bounds__(256, 2) fused_pre(
    const float* __restrict__ x,
    const float* __restrict__ g1, const float* __restrict__ b1,
    const float* __restrict__ sb,
    const float* __restrict__ g2, const float* __restrict__ b2)
{
    extern __shared__ char smem[];
    float* s_y = (float*)(smem + OFF_Y);                   // [56][132]
    const uint32_t su = (uint32_t)__cvta_generic_to_shared(smem);

    const int tid = threadIdx.x, lane = tid & 31, warp = tid >> 5;
    const int t4 = lane >> 2, q = lane & 3;
    const int c0 = lane * 4, headL = lane >> 3;

    for (int l = tid; l < 2016; l += 256)
        cpasync16(su + OFF_W + l * 16, (const char*)g_swb + l * 16);
    cp_commit();
    // zero both s_xn buffers (rows 49..55 must stay zero forever)
    for (int l = tid; l < 7616; l += 256)
        ((uint32_t*)smem)[l] = 0;
    cp_wait<0>();
    __syncthreads();

    const float4 g1v = *(const float4*)(g1 + c0);
    const float4 b1v = *(const float4*)(b1 + c0);
    const float4 g2v = *(const float4*)(g2 + c0);
    const float4 b2v = *(const float4*)(b2 + c0);

    const int h = warp >> 1, mh = warp & 1;
    const int cbase = h * 32 + mh * 16;
    const uint32_t wbase_s = su + OFF_W + (uint32_t)(h * 56 * SWS * 2);

    float4 xbuf[2][7];

    auto issue_loads = [&](int win, float4* xv) {
        const int b = win / 81, wi = win % 81;
        const int wh = wi / 9, ww = wi % 9;
        const float* xb = x + (size_t)b * 3136 * 128;
        #pragma unroll
        for (int ii = 0; ii < 7; ii++) {
            int i = warp + 8 * ii;
            if (i >= 49) continue;
            int ih = i / 7, iw = i - 7 * ih;
            int hs = wh * 7 + ih - 4, ws = ww * 7 + iw - 4;
            if ((unsigned)hs < 56u && (unsigned)ws < 56u)
                xv[ii] = *(const float4*)(xb + (hs * 56 + ws) * 128 + c0);
        }
    };
    auto ln1_store = [&](int win, const float4* xv, int bufp) {
        const int wi = win % 81;
        const int wh = wi / 9, ww = wi % 9;
        __nv_bfloat16* s_xn = (__nv_bfloat16*)(smem + bufp * XNB);
        #pragma unroll
        for (int ii = 0; ii < 7; ii++) {
            int i = warp + 8 * ii;
            if (i >= 49) continue;
            int ih = i / 7, iw = i - 7 * ih;
            int hs = wh * 7 + ih - 4, ws = ww * 7 + iw - 4;
            uint2 pk = make_uint2(0u, 0u);
            if ((unsigned)hs < 56u && (unsigned)ws < 56u) {
                float4 v = xv[ii];
                float s = v.x + v.y + v.z + v.w;
                float s2 = v.x*v.x + v.y*v.y + v.z*v.z + v.w*v.w;
                #pragma unroll
                for (int o = 16; o; o >>= 1) {
                    s  += __shfl_xor_sync(0xffffffffu, s,  o);
                    s2 += __shfl_xor_sync(0xffffffffu, s2, o);
                }
                float mu = s * 0.0078125f;
                float inv = rsqrtf(s2 * 0.0078125f - mu * mu + 1e-5f);
                pk.x = pack_bf16((v.x - mu) * inv * g1v.x + b1v.x,
                                 (v.y - mu) * inv * g1v.y + b1v.y);
                pk.y = pack_bf16((v.z - mu) * inv * g1v.z + b1v.z,
                                 (v.w - mu) * inv * g1v.w + b1v.w);
            }
            *(uint2*)&s_xn[i * SXP + c0] = pk;
        }
    };

    // prologue: win0 loads + LN1 -> buf0; win1 loads
    const int win0 = blockIdx.x * 4;
    issue_loads(win0, xbuf[0]);
    ln1_store(win0, xbuf[0], 0);
    issue_loads(win0 + 1, xbuf[1]);
    __syncthreads();

    #pragma unroll
    for (int wl = 0; wl < 4; wl++) {
        const int win = win0 + wl;
        const int b = win / 81, wi = win % 81;
        const int wh = wi / 9, ww = wi % 9;
        const uint32_t sxn_s = su + (uint32_t)((wl & 1) * XNB);

        // ---- section A: stage2 MMA(w)  +  LN1(w+1) into other buffer ----
        {
            uint32_t afr[4][4];
            const int g = lane >> 3, lr = lane & 7;
            #pragma unroll
            for (int ks = 0; ks < 4; ks++) {
                int j = ks * 16 + (g >> 1) * 8 + lr;
                if (ks == 3 && g >= 2) j = 49 + (lr & 3);   // zero rows (j>=56 pad)
                int cb = cbase + (g & 1) * 8;
                ldmx4t(afr[ks], sxn_s + (uint32_t)((j * SXP + cb) * 2));
            }
            const int crow = cbase + t4;
            #pragma unroll
            for (int np = 0; np < 4; np++) {
                float ca[4] = {0.f, 0.f, 0.f, 0.f};
                float cb4[4] = {0.f, 0.f, 0.f, 0.f};
                #pragma unroll
                for (int ks = 0; ks < 4; ks++) {
                    uint32_t bb[4];
                    if (np < 3) {
                        uint32_t ad = wbase_s + (uint32_t)((
                            (np * 16 + ((lane >> 4) & 1) * 8 + (lane & 7)) * SWS
                            + ks * 16 + ((lane >> 3) & 1) * 8) * 2);
                        ldmx4(bb, ad);
                    } else {
                        uint32_t ad = wbase_s + (uint32_t)((
                            (48 + (lane & 7)) * SWS
                            + ks * 16 + ((lane >> 3) & 1) * 8) * 2);
                        ldmx2(bb, ad);
                        bb[2] = bb[3] = 0u;
                    }
                    MMA16816(ca, afr[ks], bb[0], bb[1]);
                    if (np < 3) MMA16816(cb4, afr[ks], bb[2], bb[3]);
                }
                int i0 = (2 * np) * 8 + 2 * q;
                s_y[ i0      * SYP + crow    ] = ca[0];
                s_y[(i0 + 1) * SYP + crow    ] = ca[1];
                s_y[ i0      * SYP + crow + 8] = ca[2];
                s_y[(i0 + 1) * SYP + crow + 8] = ca[3];
                if (np < 3) {
                    int i1 = (2 * np + 1) * 8 + 2 * q;
                    s_y[ i1      * SYP + crow    ] = cb4[0];
                    s_y[(i1 + 1) * SYP + crow    ] = cb4[1];
                    s_y[ i1      * SYP + crow + 8] = cb4[2];
                    s_y[(i1 + 1) * SYP + crow + 8] = cb4[3];
                }
            }
        }
        if (wl < 3) ln1_store(win + 1, xbuf[(wl + 1) & 1], (wl + 1) & 1);
        __syncthreads();

        // ---- section B: stage3(w) + prefetch x(w+2) into the freed slot ----
        {
            const float4* xv = xbuf[wl & 1];
            #pragma unroll
            for (int ii = 0; ii < 7; ii++) {
                int i = warp + 8 * ii;
                if (i >= 49) continue;
                int ih = i / 7, iw = i - 7 * ih;
                int hs = wh * 7 + ih - 4, ws = ww * 7 + iw - 4;
                if ((unsigned)hs >= 56u || (unsigned)ws >= 56u) continue;
                float sbv = sb[headL * 49 + i];
                float4 y4 = *(const float4*)(s_y + i * SYP + c0);
                float4 v = xv[ii];
                v.x += y4.x + sbv; v.y += y4.y + sbv;
                v.z += y4.z + sbv; v.w += y4.w + sbv;
                size_t o = ((size_t)b * 3136 + hs * 56 + ws) * 128 + c0;
                *(float4*)(g_x2 + o) = v;
                float s = v.x + v.y + v.z + v.w;
                float s2 = v.x*v.x + v.y*v.y + v.z*v.z + v.w*v.w;
                #pragma unroll
                for (int os = 16; os; os >>= 1) {
                    s  += __shfl_xor_sync(0xffffffffu, s,  os);
                    s2 += __shfl_xor_sync(0xffffffffu, s2, os);
                }
                float mu = s * 0.0078125f;
                float inv = rsqrtf(s2 * 0.0078125f - mu * mu + 1e-5f);
                float n0 = (v.x - mu) * inv * g2v.x + b2v.x;
                float n1 = (v.y - mu) * inv * g2v.y + b2v.y;
                float n2 = (v.z - mu) * inv * g2v.z + b2v.z;
                float n3 = (v.w - mu) * inv * g2v.w + b2v.w;
                *(uint2*)(g_xn + o) = make_uint2(pack_bf16(n0, n1), pack_bf16(n2, n3));
            }
        }
        if (wl < 2) issue_loads(win + 2, xbuf[wl & 1]);
        if (wl < 3) __syncthreads();     // s_y reuse ordering for stage2(w+1)
    }
}

// =====================================================================
// Fused MLP with ldmatrix fragment loads (at MMA floor)
// =====================================================================
#define SXS   136
#define SW1S  136
#define SW2S  40
#define OFF_W1 34816
#define OFF_W2 (34816 + 2*8704)
#define OFF_B1 (OFF_W2 + 2*10240)
#define MLP_SMEM (OFF_B1 + 2048)

__global__ void __launch_bounds__(256, 2)
mlp_fused(const float* __restrict__ bias1, const float* __restrict__ bias2,
          float* __restrict__ out)
{
    extern __shared__ char smem[];
    const float* s_b1 = (const float*)(smem + OFF_B1);
    const uint32_t su = (uint32_t)__cvta_generic_to_shared(smem);

    const int tid = threadIdx.x, lane = tid & 31, warp = tid >> 5;
    const int t4 = lane >> 2, q = lane & 3;
    const int bm = blockIdx.x * 128;

    const int lrow = (lane & 7);
    const int lm8  = ((lane >> 3) & 1) * 8;
    const int lm16 = ((lane >> 4) & 1) * 8;

    auto load_chunk = [&](int s) {
        uint32_t buf = (uint32_t)(s & 1);
        int n0 = s * 32;
        #pragma unroll
        for (int i = 0; i < 2; i++) {
            int l = tid + 256 * i;
            int r = l >> 4, c = l & 15;
            cpasync16(su + OFF_W1 + buf * 8704 + r * 272 + c * 16,
                      g_w1t + (size_t)(n0 + r) * 128 + c * 8);
        }
        #pragma unroll
        for (int i = 0; i < 2; i++) {
            int l = tid + 256 * i;
            int r = l >> 2, c = l & 3;
            cpasync16(su + OFF_W2 + buf * 10240 + r * 80 + c * 16,
                      g_w2t + (size_t)r * 512 + n0 + c * 8);
        }
        cp_commit();
    };

    #pragma unroll
    for (int i = 0; i < 8; i++) {
        int l = tid + 256 * i;
        int r = l >> 4, c = l & 15;
        cpasync16(su + r * 272 + c * 16, g_xn + (size_t)(bm + r) * 128 + c * 8);
    }
    if (tid < 128) cpasync16(su + OFF_B1 + tid * 16, bias1 + tid * 4);
    load_chunk(0);
    load_chunk(1);

    float oacc[16][4];
    #pragma unroll
    for (int i = 0; i < 16; i++)
        #pragma unroll
        for (int j = 0; j < 4; j++) oacc[i][j] = 0.0f;

    cp_wait<1>();
    __syncthreads();

    const uint32_t abase = su + (uint32_t)(((warp * 16 + lm8 + lrow) * SXS + lm16) * 2);

    for (int s = 0; s < 16; s++) {
        const uint32_t buf = (uint32_t)(s & 1);
        const uint32_t w1s = su + OFF_W1 + buf * 8704;
        const uint32_t w2s = su + OFF_W2 + buf * 10240;

        float h[4][4];
        #pragma unroll
        for (int i = 0; i < 4; i++)
            #pragma unroll
            for (int j = 0; j < 4; j++) h[i][j] = 0.0f;

        #pragma unroll
        for (int kt = 0; kt < 8; kt++) {
            uint32_t a[4];
            ldmx4(a, abase + (uint32_t)(kt * 32));
            #pragma unroll
            for (int np = 0; np < 2; np++) {
                uint32_t bb[4];
                uint32_t ad = w1s + (uint32_t)((
                    (np * 16 + lm16 + lrow) * SW1S + kt * 16 + lm8) * 2);
                ldmx4(bb, ad);
                MMA16816(h[2*np],     a, bb[0], bb[1]);
                MMA16816(h[2*np + 1], a, bb[2], bb[3]);
            }
        }
        uint32_t a2[2][4];
        #pragma unroll
        for (int ni = 0; ni < 4; ni++) {
            int col = s * 32 + ni * 8 + 2 * q;
            float ba = s_b1[col], bb = s_b1[col + 1];
            float v0 = gelu_exact(h[ni][0] + ba), v1 = gelu_exact(h[ni][1] + bb);
            float v2 = gelu_exact(h[ni][2] + ba), v3 = gelu_exact(h[ni][3] + bb);
            a2[ni >> 1][(ni & 1) * 2 + 0] = pack_bf16(v0, v1);
            a2[ni >> 1][(ni & 1) * 2 + 1] = pack_bf16(v2, v3);
        }
        #pragma unroll
        for (int kt2 = 0; kt2 < 2; kt2++)
            #pragma unroll
            for (int np = 0; np < 8; np++) {
                uint32_t bb[4];
                uint32_t ad = w2s + (uint32_t)((
                    (np * 16 + lm16 + lrow) * SW2S + kt2 * 16 + lm8) * 2);
                ldmx4(bb, ad);
                MMA16816(oacc[2*np],     a2[kt2], bb[0], bb[1]);
                MMA16816(oacc[2*np + 1], a2[kt2], bb[2], bb[3]);
            }

        __syncthreads();
        if (s + 1 < 16) {
            if (s + 2 < 16) { load_chunk(s + 2); cp_wait<1>(); }
            else            { cp_wait<0>(); }
            __syncthreads();
        }
    }

    const int r0 = bm + warp * 16 + t4;
    #pragma unroll
    for (int ni2 = 0; ni2 < 16; ni2++) {
        int col = ni2 * 8 + 2 * q;
        float2 bs = *(const float2*)(bias2 + col);
        float2 ra = *(const float2*)(g_x2 + (size_t)r0 * 128 + col);
        float2 rb = *(const float2*)(g_x2 + (size_t)(r0 + 8) * 128 + col);
        *(float2*)(out + (size_t)r0 * 128 + col) =
            make_float2(oacc[ni2][0] + bs.x + ra.x, oacc[ni2][1] + bs.y + ra.y);
        *(float2*)(out + (size_t)(r0 + 8) * 128 + col) =
            make_float2(oacc[ni2][2] + bs.x + rb.x, oacc[ni2][3] + bs.y + rb.y);
    }
}

// ---------- launch ----------
extern "C" void kernel_launch(void* const* d_in, const int* in_sizes, int n_in,
                              void* d_out, int out_size)
{
    const float* x   = (const float*)d_in[0];
    const float* g1  = (const float*)d_in[1];
    const float* b1  = (const float*)d_in[2];
    const float* sw  = (const float*)d_in[3];
    const float* sb  = (const float*)d_in[4];
    const float* g2  = (const float*)d_in[5];
    const float* b2  = (const float*)d_in[6];
    const float* w1  = (const float*)d_in[7];
    const float* bb1 = (const float*)d_in[8];
    const float* w2  = (const float*)d_in[9];
    const float* bb2 = (const float*)d_in[10];
    float* out = (float*)d_out;

    cudaFuncSetAttribute(fused_pre, cudaFuncAttributeMaxDynamicSharedMemorySize, PRE_SMEM);
    cudaFuncSetAttribute(mlp_fused, cudaFuncAttributeMaxDynamicSharedMemorySize, MLP_SMEM);

    prep_weights<<<256, 256>>>(w1, w2, sw);
    fused_pre<<<NWIN / 4, 256, PRE_SMEM>>>(x, g1, b1, sb, g2, b2);
    mlp_fused<<<NTOK / 128, 256, MLP_SMEM>>>(bb1, bb2, out);
}

// round 15
// speedup vs baseline: 1.0287x; 1.0287x over previous
#include <cuda_runtime.h>
#include <cuda_bf16.h>
#include <math.h>
#include <stdint.h>

#define NTOK 200704
#define NWIN 5184

__device__ __nv_bfloat16 g_xn [(size_t)NTOK * 128];
__device__ float         g_x2 [(size_t)NTOK * 128];
__device__ __nv_bfloat16 g_w1t[512 * 128];        // [n][k]
__device__ __nv_bfloat16 g_w2t[128 * 512];        // [n][k]
__device__ __nv_bfloat16 g_swb[4 * 56 * 72];      // padded spatial w [h][i(56)][j(72)]

__device__ __forceinline__ void cpasync16(uint32_t s, const void* g) {
    asm volatile("cp.async.cg.shared.global [%0], [%1], 16;\n" :: "r"(s), "l"(g));
}
__device__ __forceinline__ void cp_commit() { asm volatile("cp.async.commit_group;"); }
template<int N> __device__ __forceinline__ void cp_wait() {
    asm volatile("cp.async.wait_group %0;" :: "n"(N));
}
__device__ __forceinline__ uint32_t pack_bf16(float lo, float hi) {
    uint32_t r; asm("cvt.rn.bf16x2.f32 %0, %1, %2;" : "=r"(r) : "f"(hi), "f"(lo)); return r;
}
__device__ __forceinline__ float gelu_exact(float v) {
    return 0.5f * v * (1.0f + erff(v * 0.70710678118654752f));
}
__device__ __forceinline__ void ldmx4t(uint32_t* r, uint32_t saddr) {
    asm volatile("ldmatrix.sync.aligned.m8n8.x4.trans.shared.b16 {%0,%1,%2,%3}, [%4];"
        : "=r"(r[0]), "=r"(r[1]), "=r"(r[2]), "=r"(r[3]) : "r"(saddr));
}
__device__ __forceinline__ void ldmx4(uint32_t* r, uint32_t saddr) {
    asm volatile("ldmatrix.sync.aligned.m8n8.x4.shared.b16 {%0,%1,%2,%3}, [%4];"
        : "=r"(r[0]), "=r"(r[1]), "=r"(r[2]), "=r"(r[3]) : "r"(saddr));
}
__device__ __forceinline__ void ldmx2(uint32_t* r, uint32_t saddr) {
    asm volatile("ldmatrix.sync.aligned.m8n8.x2.shared.b16 {%0,%1}, [%2];"
        : "=r"(r[0]), "=r"(r[1]) : "r"(saddr));
}
#define MMA16816(d, a, b0, b1) \
    asm volatile("mma.sync.aligned.m16n8k16.row.col.f32.bf16.bf16.f32 " \
        "{%0,%1,%2,%3},{%4,%5,%6,%7},{%8,%9},{%0,%1,%2,%3};\n" \
        : "+f"((d)[0]), "+f"((d)[1]), "+f"((d)[2]), "+f"((d)[3]) \
        : "r"((a)[0]), "r"((a)[1]), "r"((a)[2]), "r"((a)[3]), "r"(b0), "r"(b1))

// ---------- weight prep ----------
__global__ void prep_weights(const float* __restrict__ w1, const float* __restrict__ w2,
                             const float* __restrict__ sw)
{
    int t = blockIdx.x * 256 + threadIdx.x;
    if (t < 512 * 128) {
        int n = t >> 7, k = t & 127;
        g_w1t[t] = __float2bfloat16(w1[k * 512 + n]);
        int n2 = t >> 9, k2 = t & 511;
        g_w2t[t] = __float2bfloat16(w2[k2 * 128 + n2]);
    }
    if (t < 4 * 56 * 72) {
        int h = t / 4032, r = t % 4032;
        int i = r / 72, j = r % 72;
        float v = (i < 49 && j < 49) ? sw[h * 2401 + i * 49 + j] : 0.0f;
        g_swb[t] = __float2bfloat16(v);
    }
}

// ---------- fused LN1 + TC window mix + residual + LN2 (R13 version) ----------
#define SXP 136
#define SWS 72
#define SYP 132
#define OFF_W  17408                    // 64*136*2
#define OFF_Y  (OFF_W + 32256)
#define PRE_SMEM (OFF_Y + 29568)        // 79232 -> 2 CTA/SM

__global__ void __launch_bounds__(256, 2) fused_pre(
    const float* __restrict__ x,
    const float* __restrict__ g1, const float* __restrict__ b1,
    const float* __restrict__ sb,
    const float* __restrict__ g2, const float* __restrict__ b2)
{
    extern __shared__ char smem[];
    __nv_bfloat16* s_xn = (__nv_bfloat16*)smem;            // [64][136]
    float*         s_y  = (float*)(smem + OFF_Y);          // [56][132]
    const uint32_t su = (uint32_t)__cvta_generic_to_shared(smem);

    const int tid = threadIdx.x, lane = tid & 31, warp = tid >> 5;
    const int t4 = lane >> 2, q = lane & 3;
    const int c0 = lane * 4, headL = lane >> 3;

    for (int l = tid; l < 2016; l += 256)
        cpasync16(su + OFF_W + l * 16, (const char*)g_swb + l * 16);
    cp_commit();
    for (int l = tid; l < 4352; l += 256)
        ((uint32_t*)smem)[l] = 0;
    cp_wait<0>();
    __syncthreads();

    const float4 g1v = *(const float4*)(g1 + c0);
    const float4 b1v = *(const float4*)(b1 + c0);
    const float4 g2v = *(const float4*)(g2 + c0);
    const float4 b2v = *(const float4*)(b2 + c0);

    const int h = warp >> 1, mh = warp & 1;
    const int cbase = h * 32 + mh * 16;
    const uint32_t wbase_s = su + OFF_W + (uint32_t)(h * 56 * SWS * 2);

    float4 xbuf[2][7];

    auto issue_loads = [&](int win, float4* xv) {
        const int b = win / 81, wi = win % 81;
        const int wh = wi / 9, ww = wi % 9;
        const float* xb = x + (size_t)b * 3136 * 128;
        #pragma unroll
        for (int ii = 0; ii < 7; ii++) {
            int i = warp + 8 * ii;
            if (i >= 49) continue;
            int ih = i / 7, iw = i - 7 * ih;
            int hs = wh * 7 + ih - 4, ws = ww * 7 + iw - 4;
            if ((unsigned)hs < 56u && (unsigned)ws < 56u)
                xv[ii] = *(const float4*)(xb + (hs * 56 + ws) * 128 + c0);
        }
    };
    auto ln1_store = [&](int win, const float4* xv) {
        const int wi = win % 81;
        const int wh = wi / 9, ww = wi % 9;
        #pragma unroll
        for (int ii = 0; ii < 7; ii++) {
            int i = warp + 8 * ii;
            if (i >= 49) continue;
            int ih = i / 7, iw = i - 7 * ih;
            int hs = wh * 7 + ih - 4, ws = ww * 7 + iw - 4;
            uint2 pk = make_uint2(0u, 0u);
            if ((unsigned)hs < 56u && (unsigned)ws < 56u) {
                float4 v = xv[ii];
                float s = v.x + v.y + v.z + v.w;
                float s2 = v.x*v.x + v.y*v.y + v.z*v.z + v.w*v.w;
                #pragma unroll
                for (int o = 16; o; o >>= 1) {
                    s  += __shfl_xor_sync(0xffffffffu, s,  o);
                    s2 += __shfl_xor_sync(0xffffffffu, s2, o);
                }
                float mu = s * 0.0078125f;
                float inv = rsqrtf(s2 * 0.0078125f - mu * mu + 1e-5f);
                pk.x = pack_bf16((v.x - mu) * inv * g1v.x + b1v.x,
                                 (v.y - mu) * inv * g1v.y + b1v.y);
                pk.y = pack_bf16((v.z - mu) * inv * g1v.z + b1v.z,
                                 (v.w - mu) * inv * g1v.w + b1v.w);
            }
            *(uint2*)&s_xn[i * SXP + c0] = pk;
        }
    };

    issue_loads(blockIdx.x * 4, xbuf[0]);
    ln1_store(blockIdx.x * 4, xbuf[0]);
    __syncthreads();

    #pragma unroll
    for (int wl = 0; wl < 4; wl++) {
        const int win = blockIdx.x * 4 + wl;
        const int b = win / 81, wi = win % 81;
        const int wh = wi / 9, ww = wi % 9;

        // ---- stage 2: y^T = xn^T @ w^T ----
        {
            uint32_t afr[4][4];
            const int g = lane >> 3, lr = lane & 7;
            #pragma unroll
            for (int ks = 0; ks < 4; ks++) {
                int j = ks * 16 + (g >> 1) * 8 + lr;
                int cb = cbase + (g & 1) * 8;
                ldmx4t(afr[ks], su + (uint32_t)((j * SXP + cb) * 2));
            }
            const int crow = cbase + t4;
            #pragma unroll
            for (int np = 0; np < 4; np++) {
                float ca[4] = {0.f, 0.f, 0.f, 0.f};
                float cb4[4] = {0.f, 0.f, 0.f, 0.f};
                #pragma unroll
                for (int ks = 0; ks < 4; ks++) {
                    uint32_t bb[4];
                    if (np < 3) {
                        uint32_t ad = wbase_s + (uint32_t)((
                            (np * 16 + ((lane >> 4) & 1) * 8 + (lane & 7)) * SWS
                            + ks * 16 + ((lane >> 3) & 1) * 8) * 2);
                        ldmx4(bb, ad);
                    } else {
                        uint32_t ad = wbase_s + (uint32_t)((
                            (48 + (lane & 7)) * SWS
                            + ks * 16 + ((lane >> 3) & 1) * 8) * 2);
                        ldmx2(bb, ad);
                        bb[2] = bb[3] = 0u;
                    }
                    MMA16816(ca, afr[ks], bb[0], bb[1]);
                    if (np < 3) MMA16816(cb4, afr[ks], bb[2], bb[3]);
                }
                int i0 = (2 * np) * 8 + 2 * q;
                s_y[ i0      * SYP + crow    ] = ca[0];
                s_y[(i0 + 1) * SYP + crow    ] = ca[1];
                s_y[ i0      * SYP + crow + 8] = ca[2];
                s_y[(i0 + 1) * SYP + crow + 8] = ca[3];
                if (np < 3) {
                    int i1 = (2 * np + 1) * 8 + 2 * q;
                    s_y[ i1      * SYP + crow    ] = cb4[0];
                    s_y[(i1 + 1) * SYP + crow    ] = cb4[1];
                    s_y[ i1      * SYP + crow + 8] = cb4[2];
                    s_y[(i1 + 1) * SYP + crow + 8] = cb4[3];
                }
            }
        }
        __syncthreads();

        if (wl < 3) issue_loads(win + 1, xbuf[(wl + 1) & 1]);

        const float4* xv = xbuf[wl & 1];
        #pragma unroll
        for (int ii = 0; ii < 7; ii++) {
            int i = warp + 8 * ii;
            if (i >= 49) continue;
            int ih = i / 7, iw = i - 7 * ih;
            int hs = wh * 7 + ih - 4, ws = ww * 7 + iw - 4;
            if ((unsigned)hs >= 56u || (unsigned)ws >= 56u) continue;
            float sbv = sb[headL * 49 + i];
            float4 y4 = *(const float4*)(s_y + i * SYP + c0);
            float4 v = xv[ii];
            v.x += y4.x + sbv; v.y += y4.y + sbv;
            v.z += y4.z + sbv; v.w += y4.w + sbv;
            size_t o = ((size_t)b * 3136 + hs * 56 + ws) * 128 + c0;
            *(float4*)(g_x2 + o) = v;
            float s = v.x + v.y + v.z + v.w;
            float s2 = v.x*v.x + v.y*v.y + v.z*v.z + v.w*v.w;
            #pragma unroll
            for (int os = 16; os; os >>= 1) {
                s  += __shfl_xor_sync(0xffffffffu, s,  os);
                s2 += __shfl_xor_sync(0xffffffffu, s2, os);
            }
            float mu = s * 0.0078125f;
            float inv = rsqrtf(s2 * 0.0078125f - mu * mu + 1e-5f);
            float n0 = (v.x - mu) * inv * g2v.x + b2v.x;
            float n1 = (v.y - mu) * inv * g2v.y + b2v.y;
            float n2 = (v.z - mu) * inv * g2v.z + b2v.z;
            float n3 = (v.w - mu) * inv * g2v.w + b2v.w;
            *(uint2*)(g_xn + o) = make_uint2(pack_bf16(n0, n1), pack_bf16(n2, n3));
        }

        if (wl < 3) {
            ln1_store(win + 1, xbuf[(wl + 1) & 1]);
            __syncthreads();
        }
    }
}

// =====================================================================
// Fused MLP, 3-stage cp.async pipeline (1 barrier/chunk)
// =====================================================================
#define SXS   136
#define SW1S  136
#define SW2S  40
#define OFF_CH 34816                    // x tile: 128*136*2
#define CHB    18944                    // per-buffer: W1 8704 + W2 10240
#define OFF_B1 (OFF_CH + 3*CHB)         // 91648
#define MLP_SMEM (OFF_B1 + 2048)        // 93696 -> 2 CTA/SM

__global__ void __launch_bounds__(256, 2)
mlp_fused(const float* __restrict__ bias1, const float* __restrict__ bias2,
          float* __restrict__ out)
{
    extern __shared__ char smem[];
    const float* s_b1 = (const float*)(smem + OFF_B1);
    const uint32_t su = (uint32_t)__cvta_generic_to_shared(smem);

    const int tid = threadIdx.x, lane = tid & 31, warp = tid >> 5;
    const int t4 = lane >> 2, q = lane & 3;
    const int bm = blockIdx.x * 128;

    const int lrow = (lane & 7);
    const int lm8  = ((lane >> 3) & 1) * 8;
    const int lm16 = ((lane >> 4) & 1) * 8;

    auto load_chunk = [&](int s) {
        uint32_t cb = su + OFF_CH + (uint32_t)(s % 3) * CHB;
        int n0 = s * 32;
        #pragma unroll
        for (int i = 0; i < 2; i++) {               // W1 chunk [32][128]
            int l = tid + 256 * i;
            int r = l >> 4, c = l & 15;
            cpasync16(cb + r * 272 + c * 16,
                      g_w1t + (size_t)(n0 + r) * 128 + c * 8);
        }
        #pragma unroll
        for (int i = 0; i < 2; i++) {               // W2 chunk [128][32]
            int l = tid + 256 * i;
            int r = l >> 2, c = l & 3;
            cpasync16(cb + 8704 + r * 80 + c * 16,
                      g_w2t + (size_t)r * 512 + n0 + c * 8);
        }
        cp_commit();
    };

    // group 0: x tile + bias + chunk0 ; group 1: chunk1
    #pragma unroll
    for (int i = 0; i < 8; i++) {
        int l = tid + 256 * i;
        int r = l >> 4, c = l & 15;
        cpasync16(su + r * 272 + c * 16, g_xn + (size_t)(bm + r) * 128 + c * 8);
    }
    if (tid < 128) cpasync16(su + OFF_B1 + tid * 16, bias1 + tid * 4);
    {
        uint32_t cb = su + OFF_CH;
        #pragma unroll
        for (int i = 0; i < 2; i++) {
            int l = tid + 256 * i; int r = l >> 4, c = l & 15;
            cpasync16(cb + r * 272 + c * 16, g_w1t + (size_t)r * 128 + c * 8);
        }
        #pragma unroll
        for (int i = 0; i < 2; i++) {
            int l = tid + 256 * i; int r = l >> 2, c = l & 3;
            cpasync16(cb + 8704 + r * 80 + c * 16, g_w2t + (size_t)r * 512 + c * 8);
        }
        cp_commit();
    }
    load_chunk(1);

    float oacc[16][4];
    #pragma unroll
    for (int i = 0; i < 16; i++)
        #pragma unroll
        for (int j = 0; j < 4; j++) oacc[i][j] = 0.0f;

    const uint32_t abase = su + (uint32_t)(((warp * 16 + lm8 + lrow) * SXS + lm16) * 2);

    for (int s = 0; s < 16; s++) {
        if (s < 15) cp_wait<1>(); else cp_wait<0>();
        __syncthreads();                         // data(s) visible; buf (s-1)%3 free
        if (s + 2 < 16) load_chunk(s + 2);       // prefetch ahead of compute

        const uint32_t cbuf = su + OFF_CH + (uint32_t)(s % 3) * CHB;
        const uint32_t w1s = cbuf, w2s = cbuf + 8704;

        float h[4][4];
        #pragma unroll
        for (int i = 0; i < 4; i++)
            #pragma unroll
            for (int j = 0; j < 4; j++) h[i][j] = 0.0f;

        #pragma unroll
        for (int kt = 0; kt < 8; kt++) {
            uint32_t a[4];
            ldmx4(a, abase + (uint32_t)(kt * 32));
            #pragma unroll
            for (int np = 0; np < 2; np++) {
                uint32_t bb[4];
                uint32_t ad = w1s + (uint32_t)((
                    (np * 16 + lm16 + lrow) * SW1S + kt * 16 + lm8) * 2);
                ldmx4(bb, ad);
                MMA16816(h[2*np],     a, bb[0], bb[1]);
                MMA16816(h[2*np + 1], a, bb[2], bb[3]);
            }
        }
        uint32_t a2[2][4];
        #pragma unroll
        for (int ni = 0; ni < 4; ni++) {
            int col = s * 32 + ni * 8 + 2 * q;
            float ba = s_b1[col], bb = s_b1[col + 1];
            float v0 = gelu_exact(h[ni][0] + ba), v1 = gelu_exact(h[ni][1] + bb);
            float v2 = gelu_exact(h[ni][2] + ba), v3 = gelu_exact(h[ni][3] + bb);
            a2[ni >> 1][(ni & 1) * 2 + 0] = pack_bf16(v0, v1);
            a2[ni >> 1][(ni & 1) * 2 + 1] = pack_bf16(v2, v3);
        }
        #pragma unroll
        for (int kt2 = 0; kt2 < 2; kt2++)
            #pragma unroll
            for (int np = 0; np < 8; np++) {
                uint32_t bb[4];
                uint32_t ad = w2s + (uint32_t)((
                    (np * 16 + lm16 + lrow) * SW2S + kt2 * 16 + lm8) * 2);
                ldmx4(bb, ad);
                MMA16816(oacc[2*np],     a2[kt2], bb[0], bb[1]);
                MMA16816(oacc[2*np + 1], a2[kt2], bb[2], bb[3]);
            }
        // no trailing barrier: next iteration's top barrier orders buffer reuse
    }

    const int r0 = bm + warp * 16 + t4;
    #pragma unroll
    for (int ni2 = 0; ni2 < 16; ni2++) {
        int col = ni2 * 8 + 2 * q;
        float2 bs = *(const float2*)(bias2 + col);
        float2 ra = *(const float2*)(g_x2 + (size_t)r0 * 128 + col);
        float2 rb = *(const float2*)(g_x2 + (size_t)(r0 + 8) * 128 + col);
        *(float2*)(out + (size_t)r0 * 128 + col) =
            make_float2(oacc[ni2][0] + bs.x + ra.x, oacc[ni2][1] + bs.y + ra.y);
        *(float2*)(out + (size_t)(r0 + 8) * 128 + col) =
            make_float2(oacc[ni2][2] + bs.x + rb.x, oacc[ni2][3] + bs.y + rb.y);
    }
}

// ---------- launch ----------
extern "C" void kernel_launch(void* const* d_in, const int* in_sizes, int n_in,
                              void* d_out, int out_size)
{
    const float* x   = (const float*)d_in[0];
    const float* g1  = (const float*)d_in[1];
    const float* b1  = (const float*)d_in[2];
    const float* sw  = (const float*)d_in[3];
    const float* sb  = (const float*)d_in[4];
    const float* g2  = (const float*)d_in[5];
    const float* b2  = (const float*)d_in[6];
    const float* w1  = (const float*)d_in[7];
    const float* bb1 = (const float*)d_in[8];
    const float* w2  = (const float*)d_in[9];
    const float* bb2 = (const float*)d_in[10];
    float* out = (float*)d_out;

    cudaFuncSetAttribute(fused_pre, cudaFuncAttributeMaxDynamicSharedMemorySize, PRE_SMEM);
    cudaFuncSetAttribute(mlp_fused, cudaFuncAttributeMaxDynamicSharedMemorySize, MLP_SMEM);

    prep_weights<<<256, 256>>>(w1, w2, sw);
    fused_pre<<<NWIN / 4, 256, PRE_SMEM>>>(x, g1, b1, sb, g2, b2);
    mlp_fused<<<NTOK / 128, 256, MLP_SMEM>>>(bb1, bb2, out);
}